// round 15
// baseline (speedup 1.0000x reference)
#include <cuda_runtime.h>
#include <cuda_fp16.h>
#include <cstdint>
#include <math.h>

#define K1T 1152
#define K2T 2432
#define NCH1 18          // 18 chunks of 64 k
#define NCH2 38          // 36 conv + 2 residual
#define PH 66
#define PIX (PH*PH)

__device__ uint32_t g_yh[(size_t)32 * PIX * 128];   // half2 per channel pair, natural order, halo-padded
__device__ __half   g_xh[(size_t)32 * PIX * 128];   // fp16 input, natural order, halo-padded
__device__ float    g_sq[131072];
__device__ float    g_asum[131072];
__device__ __half   g_wyh[256 * K1T];               // K-major natural
__device__ __half   g_wlh[256 * K2T];               // K-major natural [wl|wp]
__device__ float    g_bsum[256];

__device__ __forceinline__ uint32_t smem_u32(const void* p) {
    uint32_t a;
    asm("{ .reg .u64 t; cvta.to.shared.u64 t, %1; cvt.u32.u64 %0, t; }" : "=r"(a) : "l"(p));
    return a;
}
__device__ __forceinline__ void cpa16(uint32_t dst, const void* src) {
    asm volatile("cp.async.cg.shared.global [%0], [%1], 16;" :: "r"(dst), "l"(src));
}
#define CPA_COMMIT()  asm volatile("cp.async.commit_group;" ::: "memory")
#define CPA_WAIT1()   asm volatile("cp.async.wait_group 1;" ::: "memory")
#define CPA_WAIT0()   asm volatile("cp.async.wait_group 0;" ::: "memory")

__device__ __forceinline__ void ldsm4(uint32_t addr, uint32_t* r) {
    asm volatile("ldmatrix.sync.aligned.m8n8.x4.shared.b16 {%0,%1,%2,%3}, [%4];"
                 : "=r"(r[0]), "=r"(r[1]), "=r"(r[2]), "=r"(r[3]) : "r"(addr));
}
__device__ __forceinline__ void mmah(float* d, uint32_t a0, uint32_t a1, uint32_t a2, uint32_t a3,
                                     uint32_t b0, uint32_t b1) {
    asm volatile("mma.sync.aligned.m16n8k16.row.col.f32.f16.f16.f32 "
                 "{%0,%1,%2,%3}, {%4,%5,%6,%7}, {%8,%9}, {%0,%1,%2,%3};"
                 : "+f"(d[0]), "+f"(d[1]), "+f"(d[2]), "+f"(d[3])
                 : "r"(a0), "r"(a1), "r"(a2), "r"(a3), "r"(b0), "r"(b1));
}
__device__ __forceinline__ void do_mmas(float acc[4][8][4], uint32_t fa[4][4], uint32_t fb[4][4])
{
    #pragma unroll
    for (int j = 0; j < 4; j++)
        #pragma unroll
        for (int mi = 0; mi < 4; mi++) {
            mmah(acc[mi][2 * j],     fa[mi][0], fa[mi][1], fa[mi][2], fa[mi][3], fb[j][0], fb[j][2]);
            mmah(acc[mi][2 * j + 1], fa[mi][0], fa[mi][1], fa[mi][2], fa[mi][3], fb[j][1], fb[j][3]);
        }
}

__device__ __forceinline__ size_t padpix(int m) {
    const int n = m >> 12, h = (m >> 6) & 63, w = m & 63;
    return (size_t)((n * PH + h + 1) * PH + (w + 1));
}

// ---- prep: smem-tiled weight transpose (coalesced reads) ----
__global__ __launch_bounds__(256)
void k0a_w(const float* __restrict__ wy, const float* __restrict__ wl, const float* __restrict__ wp)
{
    const int cobase = blockIdx.x * 32;
    const int t = threadIdx.x, kr = t >> 5, cc = t & 31;
    const int kr2 = t & 7, cc2 = t >> 3;
    __shared__ float tile[8][36];
    __shared__ float sred[256];
    float s = 0.f;
    for (int kb = 0; kb < K1T; kb += 8) {
        float v = wy[(size_t)(kb + kr) * 256 + cobase + cc];
        s += v * v;
        tile[kr][cc] = v;
        __syncthreads();
        g_wyh[(size_t)(cobase + cc2) * K1T + kb + kr2] = __float2half_rn(tile[kr2][cc2]);
        __syncthreads();
    }
    sred[t] = s;
    __syncthreads();
    if (t < 32) {
        float r = 0.f;
        #pragma unroll
        for (int j = 0; j < 8; j++) r += sred[t + 32 * j];
        g_bsum[cobase + t] = r;
    }
    for (int kb = 0; kb < K2T; kb += 8) {
        const int k = kb + kr;
        float v = (k < 2304) ? wl[(size_t)k * 256 + cobase + cc]
                             : wp[(size_t)(k - 2304) * 256 + cobase + cc];
        tile[kr][cc] = v;
        __syncthreads();
        g_wlh[(size_t)(cobase + cc2) * K2T + kb + kr2] = __float2half_rn(tile[kr2][cc2]);
        __syncthreads();
    }
}
__global__ __launch_bounds__(256)
void k0b_x(const float* __restrict__ x)
{
    const int p = blockIdx.x * 8 + (threadIdx.x >> 5), lane = threadIdx.x & 31;
    float4 v = *(const float4*)(x + (size_t)p * 128 + lane * 4);
    float s = v.x * v.x + v.y * v.y + v.z * v.z + v.w * v.w;
    #pragma unroll
    for (int o = 16; o > 0; o >>= 1) s += __shfl_xor_sync(0xffffffff, s, o);
    if (lane == 0) g_sq[p] = s;
    __half2* dh = (__half2*)(g_xh + padpix(p) * 128 + lane * 4);
    dh[0] = __floats2half2_rn(v.x, v.y);
    dh[1] = __floats2half2_rn(v.z, v.w);
}
__global__ __launch_bounds__(256)
void k0c_asum()
{
    const int p = blockIdx.x * 256 + threadIdx.x;
    const int h = (p >> 6) & 63, w = p & 63;
    float s = 0.f;
    #pragma unroll
    for (int dh = -1; dh <= 1; dh++)
        #pragma unroll
        for (int dw = -1; dw <= 1; dw++) {
            int hh = h + dh, ww = w + dw;
            if ((unsigned)hh < 64u && (unsigned)ww < 64u) s += g_sq[p + dh * 64 + dw];
        }
    g_asum[p] = s;
}

// ---- k1: fp16 yat conv, ldmatrix interleaved with MMAs ----
__global__ __launch_bounds__(128, 2)
void k1_yat(const float* __restrict__ alphap)
{
    extern __shared__ float smf[];
    const uint32_t sb = smem_u32(smf);
    const int tid = threadIdx.x, lane = tid & 31, wid = tid >> 5;
    const int wm = wid >> 1, wn = wid & 1;
    const int m_base = blockIdx.y * 128, c_base = blockIdx.x * 128;
    float* sbsum = smf + 24576;
    sbsum[tid] = g_bsum[c_base + tid];

    float acc[4][8][4];
    #pragma unroll
    for (int mi = 0; mi < 4; mi++)
        #pragma unroll
        for (int ni = 0; ni < 8; ni++)
            #pragma unroll
            for (int e = 0; e < 4; e++) acc[mi][ni][e] = 0.f;

    const int rl = lane & 15, lh = lane >> 4, sw = rl & 7;
    uint32_t aoff[4], boff[4];
    #pragma unroll
    for (int i = 0; i < 4; i++) {
        aoff[i] = (uint32_t)((wm * 64 + i * 16 + rl) * 128);
        boff[i] = (uint32_t)((wn * 64 + i * 16 + rl) * 128) + 16384u;
    }

    const int t8 = tid & 7, row0 = tid >> 3;
    const char* xb[8];
    #pragma unroll
    for (int p = 0; p < 8; p++)
        xb[p] = (const char*)g_xh + padpix(m_base + row0 + 16 * p) * 256 + t8 * 16;
    const char* wb0 = (const char*)g_wyh + (size_t)(c_base + row0) * (K1T * 2) + t8 * 16;
    const uint32_t du0 = (uint32_t)(row0 * 128 + ((t8 ^ (row0 & 7)) * 16));

    auto stage = [&](int c, int b) {
        const int khw = c >> 1;
        const int dh = khw / 3 - 1, dw = khw % 3 - 1;
        const int xoff = (dh * PH + dw) * 256 + (c & 1) * 128;
        const uint32_t base = sb + (uint32_t)b * 32768u + du0;
        const char* wsrc = wb0 + c * 128;
        #pragma unroll
        for (int p = 0; p < 8; p++) {
            cpa16(base + p * 2048u, xb[p] + xoff);
            cpa16(base + 16384u + p * 2048u, wsrc + p * (16 * K1T * 2));
        }
        CPA_COMMIT();
    };

    uint32_t fa[2][4][4], fb[2][4][4];
    auto ldfrag = [&](uint32_t bufbase, int ks, int r) {
        const uint32_t off = (uint32_t)(((2 * ks + lh) ^ sw) * 16);
        #pragma unroll
        for (int i = 0; i < 4; i++) ldsm4(bufbase + aoff[i] + off, fa[r][i]);
        #pragma unroll
        for (int i = 0; i < 4; i++) ldsm4(bufbase + boff[i] + off, fb[r][i]);
    };
    // MMA batch (rd) fused with next-batch fragment loads (into rd^1): 2 LDSM per 8 HMMA.
    auto stepld = [&](uint32_t nbase, int nks, int rd) {
        const int wr = rd ^ 1;
        const uint32_t off = (uint32_t)(((2 * nks + lh) ^ sw) * 16);
        #pragma unroll
        for (int j = 0; j < 4; j++) {
            ldsm4(nbase + aoff[j] + off, fa[wr][j]);
            ldsm4(nbase + boff[j] + off, fb[wr][j]);
            #pragma unroll
            for (int mi = 0; mi < 4; mi++) {
                mmah(acc[mi][2 * j],     fa[rd][mi][0], fa[rd][mi][1], fa[rd][mi][2], fa[rd][mi][3],
                     fb[rd][j][0], fb[rd][j][2]);
                mmah(acc[mi][2 * j + 1], fa[rd][mi][0], fa[rd][mi][1], fa[rd][mi][2], fa[rd][mi][3],
                     fb[rd][j][1], fb[rd][j][3]);
            }
        }
    };

    stage(0, 0); stage(1, 1);
    CPA_WAIT1(); __syncthreads();
    ldfrag(sb, 0, 0);

    int b = 0;
    for (int c = 0; c < NCH1; c++) {
        const uint32_t bufb = sb + (uint32_t)b * 32768u;
        stepld(bufb, 1, 0);   // mma ks0, load ks1 -> [1]
        stepld(bufb, 2, 1);   // mma ks1, load ks2 -> [0]
        stepld(bufb, 3, 0);   // mma ks2, load ks3 -> [1]
        if (c + 1 < NCH1) {
            CPA_WAIT0(); __syncthreads();
            int b2 = b + 2; if (b2 >= 3) b2 -= 3;
            if (c + 2 < NCH1) stage(c + 2, b2);
            int nb = b + 1; if (nb >= 3) nb -= 3;
            stepld(sb + (uint32_t)nb * 32768u, 0, 1);  // mma ks3, load next ks0 -> [0]
        } else {
            do_mmas(acc, fa[1], fb[1]);
        }
        if (++b == 3) b = 0;
    }

    const float scale = powf(16.f / log1pf(256.f), alphap[0]);
    #pragma unroll
    for (int mi = 0; mi < 4; mi++) {
        const int r0 = wm * 64 + mi * 16 + (lane >> 2);
        const int m0 = m_base + r0, m1 = m0 + 8;
        const float as0 = g_asum[m0], as1 = g_asum[m1];
        uint32_t* y0 = g_yh + padpix(m0) * 128;
        uint32_t* y1 = g_yh + padpix(m1) * 128;
        #pragma unroll
        for (int ni = 0; ni < 8; ni++) {
            const int cl = wn * 64 + ni * 8 + (lane & 3) * 2;
            const float bs0 = sbsum[cl], bs1 = sbsum[cl + 1];
            const float* d = acc[mi][ni];
            const float y00 = d[0] * d[0] / (as0 + bs0 - 2.f * d[0] + 1e-5f) * scale;
            const float y01 = d[1] * d[1] / (as0 + bs1 - 2.f * d[1] + 1e-5f) * scale;
            const float y10 = d[2] * d[2] / (as1 + bs0 - 2.f * d[2] + 1e-5f) * scale;
            const float y11 = d[3] * d[3] / (as1 + bs1 - 2.f * d[3] + 1e-5f) * scale;
            const int pos = (c_base + cl) >> 1;
            uint32_t h0, h1;
            asm("cvt.rn.f16x2.f32 %0, %1, %2;" : "=r"(h0) : "f"(y01), "f"(y00));
            asm("cvt.rn.f16x2.f32 %0, %1, %2;" : "=r"(h1) : "f"(y11), "f"(y10));
            y0[pos] = h0;
            y1[pos] = h1;
        }
    }
}

// ---- k2: fp16 lin conv + residual + pool ----
__global__ __launch_bounds__(128, 2)
void k2_lin(float* __restrict__ out)
{
    extern __shared__ float smf[];
    const uint32_t sb = smem_u32(smf);
    const int tid = threadIdx.x, lane = tid & 31, wid = tid >> 5;
    const int wm = wid >> 1, wn = wid & 1;
    const int m_base = blockIdx.y * 128, c_base = blockIdx.x * 128;

    float acc[4][8][4];
    #pragma unroll
    for (int mi = 0; mi < 4; mi++)
        #pragma unroll
        for (int ni = 0; ni < 8; ni++)
            #pragma unroll
            for (int e = 0; e < 4; e++) acc[mi][ni][e] = 0.f;

    const int rl = lane & 15, lh = lane >> 4, sw = rl & 7;
    uint32_t aoff[4], boff[4];
    #pragma unroll
    for (int i = 0; i < 4; i++) {
        aoff[i] = (uint32_t)((wm * 64 + i * 16 + rl) * 128);
        boff[i] = (uint32_t)((wn * 64 + i * 16 + rl) * 128) + 16384u;
    }

    const int t8 = tid & 7, row0 = tid >> 3;
    const char *yb[8], *xb2[8];
    #pragma unroll
    for (int p = 0; p < 8; p++) {
        const size_t pp = padpix(m_base + row0 + 16 * p);
        yb[p]  = (const char*)g_yh + pp * 512 + t8 * 16;
        xb2[p] = (const char*)g_xh + pp * 256 + t8 * 16;
    }
    const char* wb0 = (const char*)g_wlh + (size_t)(c_base + row0) * (K2T * 2) + t8 * 16;
    const uint32_t du0 = (uint32_t)(row0 * 128 + ((t8 ^ (row0 & 7)) * 16));

    auto stage = [&](int c, int b) {
        const uint32_t base = sb + (uint32_t)b * 32768u + du0;
        const char* wsrc = wb0 + c * 128;
        if (c < 36) {
            const int khw = c >> 2;
            const int dh = khw / 3 - 1, dw = khw % 3 - 1;
            const int yoff = (dh * PH + dw) * 512 + (c & 3) * 128;
            #pragma unroll
            for (int p = 0; p < 8; p++) {
                cpa16(base + p * 2048u, yb[p] + yoff);
                cpa16(base + 16384u + p * 2048u, wsrc + p * (16 * K2T * 2));
            }
        } else {
            const int xoff = (c - 36) * 128;
            #pragma unroll
            for (int p = 0; p < 8; p++) {
                cpa16(base + p * 2048u, xb2[p] + xoff);
                cpa16(base + 16384u + p * 2048u, wsrc + p * (16 * K2T * 2));
            }
        }
        CPA_COMMIT();
    };

    uint32_t fa[2][4][4], fb[2][4][4];
    auto ldfrag = [&](uint32_t bufbase, int ks, int r) {
        const uint32_t off = (uint32_t)(((2 * ks + lh) ^ sw) * 16);
        #pragma unroll
        for (int i = 0; i < 4; i++) ldsm4(bufbase + aoff[i] + off, fa[r][i]);
        #pragma unroll
        for (int i = 0; i < 4; i++) ldsm4(bufbase + boff[i] + off, fb[r][i]);
    };
    auto stepld = [&](uint32_t nbase, int nks, int rd) {
        const int wr = rd ^ 1;
        const uint32_t off = (uint32_t)(((2 * nks + lh) ^ sw) * 16);
        #pragma unroll
        for (int j = 0; j < 4; j++) {
            ldsm4(nbase + aoff[j] + off, fa[wr][j]);
            ldsm4(nbase + boff[j] + off, fb[wr][j]);
            #pragma unroll
            for (int mi = 0; mi < 4; mi++) {
                mmah(acc[mi][2 * j],     fa[rd][mi][0], fa[rd][mi][1], fa[rd][mi][2], fa[rd][mi][3],
                     fb[rd][j][0], fb[rd][j][2]);
                mmah(acc[mi][2 * j + 1], fa[rd][mi][0], fa[rd][mi][1], fa[rd][mi][2], fa[rd][mi][3],
                     fb[rd][j][1], fb[rd][j][3]);
            }
        }
    };

    stage(0, 0); stage(1, 1);
    CPA_WAIT1(); __syncthreads();
    ldfrag(sb, 0, 0);

    int b = 0;
    for (int c = 0; c < NCH2; c++) {
        const uint32_t bufb = sb + (uint32_t)b * 32768u;
        stepld(bufb, 1, 0);
        stepld(bufb, 2, 1);
        stepld(bufb, 3, 0);
        if (c + 1 < NCH2) {
            CPA_WAIT0(); __syncthreads();
            int b2 = b + 2; if (b2 >= 3) b2 -= 3;
            if (c + 2 < NCH2) stage(c + 2, b2);
            int nb = b + 1; if (nb >= 3) nb -= 3;
            stepld(sb + (uint32_t)nb * 32768u, 0, 1);
        } else {
            do_mmas(acc, fa[1], fb[1]);
        }
        if (++b == 3) b = 0;
    }

    __syncthreads();
    #pragma unroll
    for (int mi = 0; mi < 4; mi++) {
        const int r0 = wm * 64 + mi * 16 + (lane >> 2);
        #pragma unroll
        for (int ni = 0; ni < 8; ni++) {
            const int cl = wn * 64 + ni * 8 + (lane & 3) * 2;
            const float* d = acc[mi][ni];
            *(float2*)(smf + r0 * 132 + cl) = make_float2(d[0], d[1]);
            *(float2*)(smf + (r0 + 8) * 132 + cl) = make_float2(d[2], d[3]);
        }
    }
    __syncthreads();
    const int n = m_base >> 12, hp = ((m_base >> 6) & 63) >> 1;
    #pragma unroll
    for (int it = 0; it < 8; it++) {
        const int idx = tid + it * 128, pw = idx >> 5, ch = (idx & 31) * 4;
        float4 a0 = *(const float4*)(smf + (2 * pw) * 132 + ch);
        float4 a1 = *(const float4*)(smf + (2 * pw + 1) * 132 + ch);
        float4 a2 = *(const float4*)(smf + (64 + 2 * pw) * 132 + ch);
        float4 a3 = *(const float4*)(smf + (64 + 2 * pw + 1) * 132 + ch);
        *(float4*)(out + ((size_t)((n * 32 + hp) * 32 + pw)) * 256 + c_base + ch) =
            make_float4(0.25f * (a0.x + a1.x + a2.x + a3.x), 0.25f * (a0.y + a1.y + a2.y + a3.y),
                        0.25f * (a0.z + a1.z + a2.z + a3.z), 0.25f * (a0.w + a1.w + a2.w + a3.w));
    }
}

extern "C" void kernel_launch(void* const* d_in, const int* in_sizes, int n_in,
                              void* d_out, int out_size)
{
    const float* x  = (const float*)d_in[0];
    const float* wy = (const float*)d_in[1];
    const float* al = (const float*)d_in[2];
    const float* wl = (const float*)d_in[3];
    const float* wp = (const float*)d_in[4];
    float* out = (float*)d_out;

    cudaFuncSetAttribute(k1_yat, cudaFuncAttributeMaxDynamicSharedMemorySize, 98816);
    cudaFuncSetAttribute(k2_lin, cudaFuncAttributeMaxDynamicSharedMemorySize, 98304);

    k0a_w<<<8, 256>>>(wy, wl, wp);
    k0b_x<<<16384, 256>>>(x);
    k0c_asum<<<512, 256>>>();
    k1_yat<<<dim3(2, 1024), 128, 98816>>>(al);
    k2_lin<<<dim3(2, 1024), 128, 98304>>>(out);
}

// round 16
// speedup vs baseline: 1.1231x; 1.1231x over previous
#include <cuda_runtime.h>
#include <cuda_fp16.h>
#include <cstdint>
#include <math.h>

#define K1T 1152
#define K2T 2432
#define NCH1 18          // 18 chunks of 64 k
#define NCH2 38          // 36 conv + 2 residual
#define PH 66
#define PIX (PH*PH)

__device__ uint32_t g_yh[(size_t)32 * PIX * 128];   // half2 per channel pair, natural order, halo-padded
__device__ __half   g_xh[(size_t)32 * PIX * 128];   // fp16 input, natural order, halo-padded
__device__ float    g_sq[131072];
__device__ float    g_asum[131072];
__device__ __half   g_wyh[256 * K1T];               // K-major natural
__device__ __half   g_wlh[256 * K2T];               // K-major natural [wl|wp]
__device__ float    g_bsum[256];

__device__ __forceinline__ uint32_t smem_u32(const void* p) {
    uint32_t a;
    asm("{ .reg .u64 t; cvta.to.shared.u64 t, %1; cvt.u32.u64 %0, t; }" : "=r"(a) : "l"(p));
    return a;
}
__device__ __forceinline__ void cpa16(uint32_t dst, const void* src) {
    asm volatile("cp.async.cg.shared.global [%0], [%1], 16;" :: "r"(dst), "l"(src));
}
#define CPA_COMMIT()  asm volatile("cp.async.commit_group;" ::: "memory")
#define CPA_WAIT1()   asm volatile("cp.async.wait_group 1;" ::: "memory")
#define CPA_WAIT0()   asm volatile("cp.async.wait_group 0;" ::: "memory")

__device__ __forceinline__ void ldsm4(uint32_t addr, uint32_t* r) {
    asm volatile("ldmatrix.sync.aligned.m8n8.x4.shared.b16 {%0,%1,%2,%3}, [%4];"
                 : "=r"(r[0]), "=r"(r[1]), "=r"(r[2]), "=r"(r[3]) : "r"(addr));
}
__device__ __forceinline__ void mmah(float* d, uint32_t a0, uint32_t a1, uint32_t a2, uint32_t a3,
                                     uint32_t b0, uint32_t b1) {
    asm volatile("mma.sync.aligned.m16n8k16.row.col.f32.f16.f16.f32 "
                 "{%0,%1,%2,%3}, {%4,%5,%6,%7}, {%8,%9}, {%0,%1,%2,%3};"
                 : "+f"(d[0]), "+f"(d[1]), "+f"(d[2]), "+f"(d[3])
                 : "r"(a0), "r"(a1), "r"(a2), "r"(a3), "r"(b0), "r"(b1));
}
__device__ __forceinline__ void do_mmas(float acc[4][8][4], uint32_t fa[4][4], uint32_t fb[4][4])
{
    #pragma unroll
    for (int j = 0; j < 4; j++)
        #pragma unroll
        for (int mi = 0; mi < 4; mi++) {
            mmah(acc[mi][2 * j],     fa[mi][0], fa[mi][1], fa[mi][2], fa[mi][3], fb[j][0], fb[j][2]);
            mmah(acc[mi][2 * j + 1], fa[mi][0], fa[mi][1], fa[mi][2], fa[mi][3], fb[j][1], fb[j][3]);
        }
}

__device__ __forceinline__ size_t padpix(int m) {
    const int n = m >> 12, h = (m >> 6) & 63, w = m & 63;
    return (size_t)((n * PH + h + 1) * PH + (w + 1));
}

// ---- prep: fully parallel tiled weight transpose ----
// grid (8, 56): x = co-tile (32 cos), y<18 -> wy k-block, y>=18 -> [wl|wp] k-block.
__global__ __launch_bounds__(256)
void k0a_t(const float* __restrict__ wy, const float* __restrict__ wl, const float* __restrict__ wp)
{
    __shared__ float tile[64][33];
    const int cobase = blockIdx.x * 32;
    const bool iswy = blockIdx.y < 18;
    const int kb0 = (iswy ? blockIdx.y : blockIdx.y - 18) * 64;
    const int t = threadIdx.x, kr = t >> 5, cc = t & 31;
    #pragma unroll
    for (int i = 0; i < 8; i++) {
        const int k = kb0 + kr + 8 * i;
        float v;
        if (iswy)            v = wy[(size_t)k * 256 + cobase + cc];
        else if (k < 2304)   v = wl[(size_t)k * 256 + cobase + cc];
        else                 v = wp[(size_t)(k - 2304) * 256 + cobase + cc];
        tile[kr + 8 * i][cc] = v;
    }
    __syncthreads();
    const int co = cobase + (t >> 3), kk = (t & 7) * 8;
    __half hv[8];
    #pragma unroll
    for (int j = 0; j < 8; j++) hv[j] = __float2half_rn(tile[kk + j][t >> 3]);
    __half* dst = (iswy ? g_wyh + (size_t)co * K1T : g_wlh + (size_t)co * K2T) + kb0 + kk;
    *(uint4*)dst = *(const uint4*)hv;
}
__global__ __launch_bounds__(128)
void k0s_bsum(const float* __restrict__ wy)
{
    const int co = blockIdx.x, t = threadIdx.x;
    __shared__ float red[128];
    float s = 0.f;
    for (int k = t; k < K1T; k += 128) {
        const float v = wy[(size_t)k * 256 + co];
        s += v * v;
    }
    red[t] = s; __syncthreads();
    for (int o = 64; o > 0; o >>= 1) { if (t < o) red[t] += red[t + o]; __syncthreads(); }
    if (t == 0) g_bsum[co] = red[0];
}
__global__ __launch_bounds__(256)
void k0b_x(const float* __restrict__ x)
{
    const int p = blockIdx.x * 8 + (threadIdx.x >> 5), lane = threadIdx.x & 31;
    float4 v = *(const float4*)(x + (size_t)p * 128 + lane * 4);
    float s = v.x * v.x + v.y * v.y + v.z * v.z + v.w * v.w;
    #pragma unroll
    for (int o = 16; o > 0; o >>= 1) s += __shfl_xor_sync(0xffffffff, s, o);
    if (lane == 0) g_sq[p] = s;
    __half2* dh = (__half2*)(g_xh + padpix(p) * 128 + lane * 4);
    dh[0] = __floats2half2_rn(v.x, v.y);
    dh[1] = __floats2half2_rn(v.z, v.w);
}
__global__ __launch_bounds__(256)
void k0c_asum()
{
    const int p = blockIdx.x * 256 + threadIdx.x;
    const int h = (p >> 6) & 63, w = p & 63;
    float s = 0.f;
    #pragma unroll
    for (int dh = -1; dh <= 1; dh++)
        #pragma unroll
        for (int dw = -1; dw <= 1; dw++) {
            int hh = h + dh, ww = w + dw;
            if ((unsigned)hh < 64u && (unsigned)ww < 64u) s += g_sq[p + dh * 64 + dw];
        }
    g_asum[p] = s;
}

// ---- k1: fp16 yat conv, ldmatrix interleaved with MMAs ----
__global__ __launch_bounds__(128, 2)
void k1_yat(const float* __restrict__ alphap)
{
    extern __shared__ float smf[];
    const uint32_t sb = smem_u32(smf);
    const int tid = threadIdx.x, lane = tid & 31, wid = tid >> 5;
    const int wm = wid >> 1, wn = wid & 1;
    const int m_base = blockIdx.y * 128, c_base = blockIdx.x * 128;
    float* sbsum = smf + 24576;
    sbsum[tid] = g_bsum[c_base + tid];

    float acc[4][8][4];
    #pragma unroll
    for (int mi = 0; mi < 4; mi++)
        #pragma unroll
        for (int ni = 0; ni < 8; ni++)
            #pragma unroll
            for (int e = 0; e < 4; e++) acc[mi][ni][e] = 0.f;

    const int rl = lane & 15, lh = lane >> 4, sw = rl & 7;
    uint32_t aoff[4], boff[4];
    #pragma unroll
    for (int i = 0; i < 4; i++) {
        aoff[i] = (uint32_t)((wm * 64 + i * 16 + rl) * 128);
        boff[i] = (uint32_t)((wn * 64 + i * 16 + rl) * 128) + 16384u;
    }

    const int t8 = tid & 7, row0 = tid >> 3;
    const char* xb[8];
    #pragma unroll
    for (int p = 0; p < 8; p++)
        xb[p] = (const char*)g_xh + padpix(m_base + row0 + 16 * p) * 256 + t8 * 16;
    const char* wb0 = (const char*)g_wyh + (size_t)(c_base + row0) * (K1T * 2) + t8 * 16;
    const uint32_t du0 = (uint32_t)(row0 * 128 + ((t8 ^ (row0 & 7)) * 16));

    auto stage = [&](int c, int b) {
        const int khw = c >> 1;
        const int dh = khw / 3 - 1, dw = khw % 3 - 1;
        const int xoff = (dh * PH + dw) * 256 + (c & 1) * 128;
        const uint32_t base = sb + (uint32_t)b * 32768u + du0;
        const char* wsrc = wb0 + c * 128;
        #pragma unroll
        for (int p = 0; p < 8; p++) {
            cpa16(base + p * 2048u, xb[p] + xoff);
            cpa16(base + 16384u + p * 2048u, wsrc + p * (16 * K1T * 2));
        }
        CPA_COMMIT();
    };

    uint32_t fa[2][4][4], fb[2][4][4];
    auto ldfrag = [&](uint32_t bufbase, int ks, int r) {
        const uint32_t off = (uint32_t)(((2 * ks + lh) ^ sw) * 16);
        #pragma unroll
        for (int i = 0; i < 4; i++) ldsm4(bufbase + aoff[i] + off, fa[r][i]);
        #pragma unroll
        for (int i = 0; i < 4; i++) ldsm4(bufbase + boff[i] + off, fb[r][i]);
    };
    auto stepld = [&](uint32_t nbase, int nks, int rd) {
        const int wr = rd ^ 1;
        const uint32_t off = (uint32_t)(((2 * nks + lh) ^ sw) * 16);
        #pragma unroll
        for (int j = 0; j < 4; j++) {
            ldsm4(nbase + aoff[j] + off, fa[wr][j]);
            ldsm4(nbase + boff[j] + off, fb[wr][j]);
            #pragma unroll
            for (int mi = 0; mi < 4; mi++) {
                mmah(acc[mi][2 * j],     fa[rd][mi][0], fa[rd][mi][1], fa[rd][mi][2], fa[rd][mi][3],
                     fb[rd][j][0], fb[rd][j][2]);
                mmah(acc[mi][2 * j + 1], fa[rd][mi][0], fa[rd][mi][1], fa[rd][mi][2], fa[rd][mi][3],
                     fb[rd][j][1], fb[rd][j][3]);
            }
        }
    };

    stage(0, 0); stage(1, 1);
    CPA_WAIT1(); __syncthreads();
    ldfrag(sb, 0, 0);

    int b = 0;
    for (int c = 0; c < NCH1; c++) {
        const uint32_t bufb = sb + (uint32_t)b * 32768u;
        stepld(bufb, 1, 0);
        stepld(bufb, 2, 1);
        stepld(bufb, 3, 0);
        if (c + 1 < NCH1) {
            CPA_WAIT0(); __syncthreads();
            int b2 = b + 2; if (b2 >= 3) b2 -= 3;
            if (c + 2 < NCH1) stage(c + 2, b2);
            int nb = b + 1; if (nb >= 3) nb -= 3;
            stepld(sb + (uint32_t)nb * 32768u, 0, 1);
        } else {
            do_mmas(acc, fa[1], fb[1]);
        }
        if (++b == 3) b = 0;
    }

    const float scale = powf(16.f / log1pf(256.f), alphap[0]);
    #pragma unroll
    for (int mi = 0; mi < 4; mi++) {
        const int r0 = wm * 64 + mi * 16 + (lane >> 2);
        const int m0 = m_base + r0, m1 = m0 + 8;
        const float as0 = g_asum[m0], as1 = g_asum[m1];
        uint32_t* y0 = g_yh + padpix(m0) * 128;
        uint32_t* y1 = g_yh + padpix(m1) * 128;
        #pragma unroll
        for (int ni = 0; ni < 8; ni++) {
            const int cl = wn * 64 + ni * 8 + (lane & 3) * 2;
            const float bs0 = sbsum[cl], bs1 = sbsum[cl + 1];
            const float* d = acc[mi][ni];
            const float y00 = d[0] * d[0] / (as0 + bs0 - 2.f * d[0] + 1e-5f) * scale;
            const float y01 = d[1] * d[1] / (as0 + bs1 - 2.f * d[1] + 1e-5f) * scale;
            const float y10 = d[2] * d[2] / (as1 + bs0 - 2.f * d[2] + 1e-5f) * scale;
            const float y11 = d[3] * d[3] / (as1 + bs1 - 2.f * d[3] + 1e-5f) * scale;
            const int pos = (c_base + cl) >> 1;
            uint32_t h0, h1;
            asm("cvt.rn.f16x2.f32 %0, %1, %2;" : "=r"(h0) : "f"(y01), "f"(y00));
            asm("cvt.rn.f16x2.f32 %0, %1, %2;" : "=r"(h1) : "f"(y11), "f"(y10));
            y0[pos] = h0;
            y1[pos] = h1;
        }
    }
}

// ---- k2: fp16 lin conv + residual + pool ----
__global__ __launch_bounds__(128, 2)
void k2_lin(float* __restrict__ out)
{
    extern __shared__ float smf[];
    const uint32_t sb = smem_u32(smf);
    const int tid = threadIdx.x, lane = tid & 31, wid = tid >> 5;
    const int wm = wid >> 1, wn = wid & 1;
    const int m_base = blockIdx.y * 128, c_base = blockIdx.x * 128;

    float acc[4][8][4];
    #pragma unroll
    for (int mi = 0; mi < 4; mi++)
        #pragma unroll
        for (int ni = 0; ni < 8; ni++)
            #pragma unroll
            for (int e = 0; e < 4; e++) acc[mi][ni][e] = 0.f;

    const int rl = lane & 15, lh = lane >> 4, sw = rl & 7;
    uint32_t aoff[4], boff[4];
    #pragma unroll
    for (int i = 0; i < 4; i++) {
        aoff[i] = (uint32_t)((wm * 64 + i * 16 + rl) * 128);
        boff[i] = (uint32_t)((wn * 64 + i * 16 + rl) * 128) + 16384u;
    }

    const int t8 = tid & 7, row0 = tid >> 3;
    const char *yb[8], *xb2[8];
    #pragma unroll
    for (int p = 0; p < 8; p++) {
        const size_t pp = padpix(m_base + row0 + 16 * p);
        yb[p]  = (const char*)g_yh + pp * 512 + t8 * 16;
        xb2[p] = (const char*)g_xh + pp * 256 + t8 * 16;
    }
    const char* wb0 = (const char*)g_wlh + (size_t)(c_base + row0) * (K2T * 2) + t8 * 16;
    const uint32_t du0 = (uint32_t)(row0 * 128 + ((t8 ^ (row0 & 7)) * 16));

    auto stage = [&](int c, int b) {
        const uint32_t base = sb + (uint32_t)b * 32768u + du0;
        const char* wsrc = wb0 + c * 128;
        if (c < 36) {
            const int khw = c >> 2;
            const int dh = khw / 3 - 1, dw = khw % 3 - 1;
            const int yoff = (dh * PH + dw) * 512 + (c & 3) * 128;
            #pragma unroll
            for (int p = 0; p < 8; p++) {
                cpa16(base + p * 2048u, yb[p] + yoff);
                cpa16(base + 16384u + p * 2048u, wsrc + p * (16 * K2T * 2));
            }
        } else {
            const int xoff = (c - 36) * 128;
            #pragma unroll
            for (int p = 0; p < 8; p++) {
                cpa16(base + p * 2048u, xb2[p] + xoff);
                cpa16(base + 16384u + p * 2048u, wsrc + p * (16 * K2T * 2));
            }
        }
        CPA_COMMIT();
    };

    uint32_t fa[2][4][4], fb[2][4][4];
    auto ldfrag = [&](uint32_t bufbase, int ks, int r) {
        const uint32_t off = (uint32_t)(((2 * ks + lh) ^ sw) * 16);
        #pragma unroll
        for (int i = 0; i < 4; i++) ldsm4(bufbase + aoff[i] + off, fa[r][i]);
        #pragma unroll
        for (int i = 0; i < 4; i++) ldsm4(bufbase + boff[i] + off, fb[r][i]);
    };
    auto stepld = [&](uint32_t nbase, int nks, int rd) {
        const int wr = rd ^ 1;
        const uint32_t off = (uint32_t)(((2 * nks + lh) ^ sw) * 16);
        #pragma unroll
        for (int j = 0; j < 4; j++) {
            ldsm4(nbase + aoff[j] + off, fa[wr][j]);
            ldsm4(nbase + boff[j] + off, fb[wr][j]);
            #pragma unroll
            for (int mi = 0; mi < 4; mi++) {
                mmah(acc[mi][2 * j],     fa[rd][mi][0], fa[rd][mi][1], fa[rd][mi][2], fa[rd][mi][3],
                     fb[rd][j][0], fb[rd][j][2]);
                mmah(acc[mi][2 * j + 1], fa[rd][mi][0], fa[rd][mi][1], fa[rd][mi][2], fa[rd][mi][3],
                     fb[rd][j][1], fb[rd][j][3]);
            }
        }
    };

    stage(0, 0); stage(1, 1);
    CPA_WAIT1(); __syncthreads();
    ldfrag(sb, 0, 0);

    int b = 0;
    for (int c = 0; c < NCH2; c++) {
        const uint32_t bufb = sb + (uint32_t)b * 32768u;
        stepld(bufb, 1, 0);
        stepld(bufb, 2, 1);
        stepld(bufb, 3, 0);
        if (c + 1 < NCH2) {
            CPA_WAIT0(); __syncthreads();
            int b2 = b + 2; if (b2 >= 3) b2 -= 3;
            if (c + 2 < NCH2) stage(c + 2, b2);
            int nb = b + 1; if (nb >= 3) nb -= 3;
            stepld(sb + (uint32_t)nb * 32768u, 0, 1);
        } else {
            do_mmas(acc, fa[1], fb[1]);
        }
        if (++b == 3) b = 0;
    }

    __syncthreads();
    #pragma unroll
    for (int mi = 0; mi < 4; mi++) {
        const int r0 = wm * 64 + mi * 16 + (lane >> 2);
        #pragma unroll
        for (int ni = 0; ni < 8; ni++) {
            const int cl = wn * 64 + ni * 8 + (lane & 3) * 2;
            const float* d = acc[mi][ni];
            *(float2*)(smf + r0 * 132 + cl) = make_float2(d[0], d[1]);
            *(float2*)(smf + (r0 + 8) * 132 + cl) = make_float2(d[2], d[3]);
        }
    }
    __syncthreads();
    const int n = m_base >> 12, hp = ((m_base >> 6) & 63) >> 1;
    #pragma unroll
    for (int it = 0; it < 8; it++) {
        const int idx = tid + it * 128, pw = idx >> 5, ch = (idx & 31) * 4;
        float4 a0 = *(const float4*)(smf + (2 * pw) * 132 + ch);
        float4 a1 = *(const float4*)(smf + (2 * pw + 1) * 132 + ch);
        float4 a2 = *(const float4*)(smf + (64 + 2 * pw) * 132 + ch);
        float4 a3 = *(const float4*)(smf + (64 + 2 * pw + 1) * 132 + ch);
        *(float4*)(out + ((size_t)((n * 32 + hp) * 32 + pw)) * 256 + c_base + ch) =
            make_float4(0.25f * (a0.x + a1.x + a2.x + a3.x), 0.25f * (a0.y + a1.y + a2.y + a3.y),
                        0.25f * (a0.z + a1.z + a2.z + a3.z), 0.25f * (a0.w + a1.w + a2.w + a3.w));
    }
}

extern "C" void kernel_launch(void* const* d_in, const int* in_sizes, int n_in,
                              void* d_out, int out_size)
{
    const float* x  = (const float*)d_in[0];
    const float* wy = (const float*)d_in[1];
    const float* al = (const float*)d_in[2];
    const float* wl = (const float*)d_in[3];
    const float* wp = (const float*)d_in[4];
    float* out = (float*)d_out;

    cudaFuncSetAttribute(k1_yat, cudaFuncAttributeMaxDynamicSharedMemorySize, 98816);
    cudaFuncSetAttribute(k2_lin, cudaFuncAttributeMaxDynamicSharedMemorySize, 98304);

    k0a_t<<<dim3(8, 56), 256>>>(wy, wl, wp);
    k0s_bsum<<<256, 128>>>(wy);
    k0b_x<<<16384, 256>>>(x);
    k0c_asum<<<512, 256>>>();
    k1_yat<<<dim3(2, 1024), 128, 98816>>>(al);
    k2_lin<<<dim3(2, 1024), 128, 98304>>>(out);
}

// round 17
// speedup vs baseline: 1.5636x; 1.3922x over previous
#include <cuda_runtime.h>
#include <cuda_fp16.h>
#include <cstdint>
#include <math.h>

#define K1T 1152
#define K2T 4608         // 16 y-taps x 256 + 4 x-taps x 128
#define NCH1 18
#define NCH2 72
#define PH 66
#define PIX (PH*PH)

__device__ uint32_t g_yh[(size_t)32 * PIX * 128];   // half2 per channel pair, halo-padded
__device__ __half   g_xh[(size_t)32 * PIX * 128];   // fp16 input, halo-padded
__device__ float    g_sq[131072];
__device__ float    g_asum[131072];
__device__ __half   g_wyh[256 * K1T];               // K-major natural
__device__ __half   g_w2h[256 * K2T];               // K-major pooled-fused weights
__device__ float    g_bsum[256];

__device__ __forceinline__ uint32_t smem_u32(const void* p) {
    uint32_t a;
    asm("{ .reg .u64 t; cvta.to.shared.u64 t, %1; cvt.u32.u64 %0, t; }" : "=r"(a) : "l"(p));
    return a;
}
__device__ __forceinline__ void cpa16(uint32_t dst, const void* src) {
    asm volatile("cp.async.cg.shared.global [%0], [%1], 16;" :: "r"(dst), "l"(src));
}
#define CPA_COMMIT()  asm volatile("cp.async.commit_group;" ::: "memory")
#define CPA_WAIT1()   asm volatile("cp.async.wait_group 1;" ::: "memory")
#define CPA_WAIT0()   asm volatile("cp.async.wait_group 0;" ::: "memory")

__device__ __forceinline__ void ldsm4(uint32_t addr, uint32_t* r) {
    asm volatile("ldmatrix.sync.aligned.m8n8.x4.shared.b16 {%0,%1,%2,%3}, [%4];"
                 : "=r"(r[0]), "=r"(r[1]), "=r"(r[2]), "=r"(r[3]) : "r"(addr));
}
__device__ __forceinline__ void mmah(float* d, uint32_t a0, uint32_t a1, uint32_t a2, uint32_t a3,
                                     uint32_t b0, uint32_t b1) {
    asm volatile("mma.sync.aligned.m16n8k16.row.col.f32.f16.f16.f32 "
                 "{%0,%1,%2,%3}, {%4,%5,%6,%7}, {%8,%9}, {%0,%1,%2,%3};"
                 : "+f"(d[0]), "+f"(d[1]), "+f"(d[2]), "+f"(d[3])
                 : "r"(a0), "r"(a1), "r"(a2), "r"(a3), "r"(b0), "r"(b1));
}
__device__ __forceinline__ void do_mmas(float acc[4][8][4], uint32_t fa[4][4], uint32_t fb[4][4])
{
    #pragma unroll
    for (int j = 0; j < 4; j++)
        #pragma unroll
        for (int mi = 0; mi < 4; mi++) {
            mmah(acc[mi][2 * j],     fa[mi][0], fa[mi][1], fa[mi][2], fa[mi][3], fb[j][0], fb[j][2]);
            mmah(acc[mi][2 * j + 1], fa[mi][0], fa[mi][1], fa[mi][2], fa[mi][3], fb[j][1], fb[j][3]);
        }
}

__device__ __forceinline__ size_t padpix(int m) {
    const int n = m >> 12, h = (m >> 6) & 63, w = m & 63;
    return (size_t)((n * PH + h + 1) * PH + (w + 1));
}

// fused pooled weight: k in [0,4608)
__device__ __forceinline__ float w2val(const float* wl, const float* wp, int k, int co)
{
    if (k < 4096) {
        const int tap = k >> 8, ci = k & 255;
        const int u = tap >> 2, v = tap & 3;
        float s = 0.f;
        #pragma unroll
        for (int i = 0; i < 2; i++)
            #pragma unroll
            for (int j = 0; j < 2; j++) {
                const int a = u - i, b = v - j;
                if (a >= 0 && a < 3 && b >= 0 && b < 3)
                    s += wl[(size_t)((a * 3 + b) * 256 + ci) * 256 + co];
            }
        return 0.25f * s;
    }
    const int ci = (k - 4096) & 127;
    return 0.25f * wp[(size_t)ci * 256 + co];
}

// ---- prep: parallel tiled weight transpose. grid (8, 18+72) ----
__global__ __launch_bounds__(256)
void k0a_t(const float* __restrict__ wy, const float* __restrict__ wl, const float* __restrict__ wp)
{
    __shared__ float tile[64][33];
    const int cobase = blockIdx.x * 32;
    const bool iswy = blockIdx.y < 18;
    const int kb0 = (iswy ? blockIdx.y : blockIdx.y - 18) * 64;
    const int t = threadIdx.x, kr = t >> 5, cc = t & 31;
    #pragma unroll
    for (int i = 0; i < 8; i++) {
        const int k = kb0 + kr + 8 * i;
        tile[kr + 8 * i][cc] = iswy ? wy[(size_t)k * 256 + cobase + cc]
                                    : w2val(wl, wp, k, cobase + cc);
    }
    __syncthreads();
    const int co = cobase + (t >> 3), kk = (t & 7) * 8;
    __half hv[8];
    #pragma unroll
    for (int j = 0; j < 8; j++) hv[j] = __float2half_rn(tile[kk + j][t >> 3]);
    __half* dst = (iswy ? g_wyh + (size_t)co * K1T : g_w2h + (size_t)co * K2T) + kb0 + kk;
    *(uint4*)dst = *(const uint4*)hv;
}
__global__ __launch_bounds__(128)
void k0s_bsum(const float* __restrict__ wy)
{
    const int co = blockIdx.x, t = threadIdx.x;
    __shared__ float red[128];
    float s = 0.f;
    for (int k = t; k < K1T; k += 128) {
        const float v = wy[(size_t)k * 256 + co];
        s += v * v;
    }
    red[t] = s; __syncthreads();
    for (int o = 64; o > 0; o >>= 1) { if (t < o) red[t] += red[t + o]; __syncthreads(); }
    if (t == 0) g_bsum[co] = red[0];
}
__global__ __launch_bounds__(256)
void k0b_x(const float* __restrict__ x)
{
    const int p = blockIdx.x * 8 + (threadIdx.x >> 5), lane = threadIdx.x & 31;
    float4 v = *(const float4*)(x + (size_t)p * 128 + lane * 4);
    float s = v.x * v.x + v.y * v.y + v.z * v.z + v.w * v.w;
    #pragma unroll
    for (int o = 16; o > 0; o >>= 1) s += __shfl_xor_sync(0xffffffff, s, o);
    if (lane == 0) g_sq[p] = s;
    __half2* dh = (__half2*)(g_xh + padpix(p) * 128 + lane * 4);
    dh[0] = __floats2half2_rn(v.x, v.y);
    dh[1] = __floats2half2_rn(v.z, v.w);
}
__global__ __launch_bounds__(256)
void k0c_asum()
{
    const int p = blockIdx.x * 256 + threadIdx.x;
    const int h = (p >> 6) & 63, w = p & 63;
    float s = 0.f;
    #pragma unroll
    for (int dh = -1; dh <= 1; dh++)
        #pragma unroll
        for (int dw = -1; dw <= 1; dw++) {
            int hh = h + dh, ww = w + dw;
            if ((unsigned)hh < 64u && (unsigned)ww < 64u) s += g_sq[p + dh * 64 + dw];
        }
    g_asum[p] = s;
}

// ---- k1: fp16 yat conv (unchanged from R16) ----
__global__ __launch_bounds__(128, 2)
void k1_yat(const float* __restrict__ alphap)
{
    extern __shared__ float smf[];
    const uint32_t sb = smem_u32(smf);
    const int tid = threadIdx.x, lane = tid & 31, wid = tid >> 5;
    const int wm = wid >> 1, wn = wid & 1;
    const int m_base = blockIdx.y * 128, c_base = blockIdx.x * 128;
    float* sbsum = smf + 24576;
    sbsum[tid] = g_bsum[c_base + tid];

    float acc[4][8][4];
    #pragma unroll
    for (int mi = 0; mi < 4; mi++)
        #pragma unroll
        for (int ni = 0; ni < 8; ni++)
            #pragma unroll
            for (int e = 0; e < 4; e++) acc[mi][ni][e] = 0.f;

    const int rl = lane & 15, lh = lane >> 4, sw = rl & 7;
    uint32_t aoff[4], boff[4];
    #pragma unroll
    for (int i = 0; i < 4; i++) {
        aoff[i] = (uint32_t)((wm * 64 + i * 16 + rl) * 128);
        boff[i] = (uint32_t)((wn * 64 + i * 16 + rl) * 128) + 16384u;
    }

    const int t8 = tid & 7, row0 = tid >> 3;
    const char* xb[8];
    #pragma unroll
    for (int p = 0; p < 8; p++)
        xb[p] = (const char*)g_xh + padpix(m_base + row0 + 16 * p) * 256 + t8 * 16;
    const char* wb0 = (const char*)g_wyh + (size_t)(c_base + row0) * (K1T * 2) + t8 * 16;
    const uint32_t du0 = (uint32_t)(row0 * 128 + ((t8 ^ (row0 & 7)) * 16));

    auto stage = [&](int c, int b) {
        const int khw = c >> 1;
        const int dh = khw / 3 - 1, dw = khw % 3 - 1;
        const int xoff = (dh * PH + dw) * 256 + (c & 1) * 128;
        const uint32_t base = sb + (uint32_t)b * 32768u + du0;
        const char* wsrc = wb0 + c * 128;
        #pragma unroll
        for (int p = 0; p < 8; p++) {
            cpa16(base + p * 2048u, xb[p] + xoff);
            cpa16(base + 16384u + p * 2048u, wsrc + p * (16 * K1T * 2));
        }
        CPA_COMMIT();
    };

    uint32_t fa[2][4][4], fb[2][4][4];
    auto ldfrag = [&](uint32_t bufbase, int ks, int r) {
        const uint32_t off = (uint32_t)(((2 * ks + lh) ^ sw) * 16);
        #pragma unroll
        for (int i = 0; i < 4; i++) ldsm4(bufbase + aoff[i] + off, fa[r][i]);
        #pragma unroll
        for (int i = 0; i < 4; i++) ldsm4(bufbase + boff[i] + off, fb[r][i]);
    };
    auto stepld = [&](uint32_t nbase, int nks, int rd) {
        const int wr = rd ^ 1;
        const uint32_t off = (uint32_t)(((2 * nks + lh) ^ sw) * 16);
        #pragma unroll
        for (int j = 0; j < 4; j++) {
            ldsm4(nbase + aoff[j] + off, fa[wr][j]);
            ldsm4(nbase + boff[j] + off, fb[wr][j]);
            #pragma unroll
            for (int mi = 0; mi < 4; mi++) {
                mmah(acc[mi][2 * j],     fa[rd][mi][0], fa[rd][mi][1], fa[rd][mi][2], fa[rd][mi][3],
                     fb[rd][j][0], fb[rd][j][2]);
                mmah(acc[mi][2 * j + 1], fa[rd][mi][0], fa[rd][mi][1], fa[rd][mi][2], fa[rd][mi][3],
                     fb[rd][j][1], fb[rd][j][3]);
            }
        }
    };

    stage(0, 0); stage(1, 1);
    CPA_WAIT1(); __syncthreads();
    ldfrag(sb, 0, 0);

    int b = 0;
    for (int c = 0; c < NCH1; c++) {
        const uint32_t bufb = sb + (uint32_t)b * 32768u;
        stepld(bufb, 1, 0);
        stepld(bufb, 2, 1);
        stepld(bufb, 3, 0);
        if (c + 1 < NCH1) {
            CPA_WAIT0(); __syncthreads();
            int b2 = b + 2; if (b2 >= 3) b2 -= 3;
            if (c + 2 < NCH1) stage(c + 2, b2);
            int nb = b + 1; if (nb >= 3) nb -= 3;
            stepld(sb + (uint32_t)nb * 32768u, 0, 1);
        } else {
            do_mmas(acc, fa[1], fb[1]);
        }
        if (++b == 3) b = 0;
    }

    const float scale = powf(16.f / log1pf(256.f), alphap[0]);
    #pragma unroll
    for (int mi = 0; mi < 4; mi++) {
        const int r0 = wm * 64 + mi * 16 + (lane >> 2);
        const int m0 = m_base + r0, m1 = m0 + 8;
        const float as0 = g_asum[m0], as1 = g_asum[m1];
        uint32_t* y0 = g_yh + padpix(m0) * 128;
        uint32_t* y1 = g_yh + padpix(m1) * 128;
        #pragma unroll
        for (int ni = 0; ni < 8; ni++) {
            const int cl = wn * 64 + ni * 8 + (lane & 3) * 2;
            const float bs0 = sbsum[cl], bs1 = sbsum[cl + 1];
            const float* d = acc[mi][ni];
            const float y00 = d[0] * d[0] / (as0 + bs0 - 2.f * d[0] + 1e-5f) * scale;
            const float y01 = d[1] * d[1] / (as0 + bs1 - 2.f * d[1] + 1e-5f) * scale;
            const float y10 = d[2] * d[2] / (as1 + bs0 - 2.f * d[2] + 1e-5f) * scale;
            const float y11 = d[3] * d[3] / (as1 + bs1 - 2.f * d[3] + 1e-5f) * scale;
            const int pos = (c_base + cl) >> 1;
            uint32_t h0, h1;
            asm("cvt.rn.f16x2.f32 %0, %1, %2;" : "=r"(h0) : "f"(y01), "f"(y00));
            asm("cvt.rn.f16x2.f32 %0, %1, %2;" : "=r"(h1) : "f"(y11), "f"(y10));
            y0[pos] = h0;
            y1[pos] = h1;
        }
    }
}

// ---- k2: pooled-fused stride-2 conv. M=32768 pooled pixels, K=4608. ----
__global__ __launch_bounds__(128, 2)
void k2_lin(float* __restrict__ out)
{
    extern __shared__ float smf[];
    const uint32_t sb = smem_u32(smf);
    const int tid = threadIdx.x, lane = tid & 31, wid = tid >> 5;
    const int wm = wid >> 1, wn = wid & 1;
    const int m_base = blockIdx.y * 128, c_base = blockIdx.x * 128;

    float acc[4][8][4];
    #pragma unroll
    for (int mi = 0; mi < 4; mi++)
        #pragma unroll
        for (int ni = 0; ni < 8; ni++)
            #pragma unroll
            for (int e = 0; e < 4; e++) acc[mi][ni][e] = 0.f;

    const int rl = lane & 15, lh = lane >> 4, sw = rl & 7;
    uint32_t aoff[4], boff[4];
    #pragma unroll
    for (int i = 0; i < 4; i++) {
        aoff[i] = (uint32_t)((wm * 64 + i * 16 + rl) * 128);
        boff[i] = (uint32_t)((wn * 64 + i * 16 + rl) * 128) + 16384u;
    }

    const int t8 = tid & 7, row0 = tid >> 3;
    // pooled-pixel tap bases: m -> (n, hp, wp)
    const char *ybp[8], *xbp[8];
    #pragma unroll
    for (int p = 0; p < 8; p++) {
        const int m = m_base + row0 + 16 * p;
        const int n = m >> 10, hp = (m >> 5) & 31, wp = m & 31;
        ybp[p] = (const char*)g_yh + (size_t)((n * PH + 2 * hp) * PH + 2 * wp) * 512 + t8 * 16;
        xbp[p] = (const char*)g_xh + (size_t)((n * PH + 2 * hp + 1) * PH + 2 * wp + 1) * 256 + t8 * 16;
    }
    const char* wb0 = (const char*)g_w2h + (size_t)(c_base + row0) * (K2T * 2) + t8 * 16;
    const uint32_t du0 = (uint32_t)(row0 * 128 + ((t8 ^ (row0 & 7)) * 16));

    auto stage = [&](int c, int b) {
        const uint32_t base = sb + (uint32_t)b * 32768u + du0;
        const char* wsrc = wb0 + c * 128;
        if (c < 64) {
            const int tap = c >> 2, u = tap >> 2, v = tap & 3;
            const int yoff = (u * PH + v) * 512 + (c & 3) * 128;
            #pragma unroll
            for (int p = 0; p < 8; p++) {
                cpa16(base + p * 2048u, ybp[p] + yoff);
                cpa16(base + 16384u + p * 2048u, wsrc + p * (16 * K2T * 2));
            }
        } else {
            const int r = c - 64, tap2 = r >> 1;
            const int xoff = ((tap2 >> 1) * PH + (tap2 & 1)) * 256 + (r & 1) * 128;
            #pragma unroll
            for (int p = 0; p < 8; p++) {
                cpa16(base + p * 2048u, xbp[p] + xoff);
                cpa16(base + 16384u + p * 2048u, wsrc + p * (16 * K2T * 2));
            }
        }
        CPA_COMMIT();
    };

    uint32_t fa[2][4][4], fb[2][4][4];
    auto ldfrag = [&](uint32_t bufbase, int ks, int r) {
        const uint32_t off = (uint32_t)(((2 * ks + lh) ^ sw) * 16);
        #pragma unroll
        for (int i = 0; i < 4; i++) ldsm4(bufbase + aoff[i] + off, fa[r][i]);
        #pragma unroll
        for (int i = 0; i < 4; i++) ldsm4(bufbase + boff[i] + off, fb[r][i]);
    };
    auto stepld = [&](uint32_t nbase, int nks, int rd) {
        const int wr = rd ^ 1;
        const uint32_t off = (uint32_t)(((2 * nks + lh) ^ sw) * 16);
        #pragma unroll
        for (int j = 0; j < 4; j++) {
            ldsm4(nbase + aoff[j] + off, fa[wr][j]);
            ldsm4(nbase + boff[j] + off, fb[wr][j]);
            #pragma unroll
            for (int mi = 0; mi < 4; mi++) {
                mmah(acc[mi][2 * j],     fa[rd][mi][0], fa[rd][mi][1], fa[rd][mi][2], fa[rd][mi][3],
                     fb[rd][j][0], fb[rd][j][2]);
                mmah(acc[mi][2 * j + 1], fa[rd][mi][0], fa[rd][mi][1], fa[rd][mi][2], fa[rd][mi][3],
                     fb[rd][j][1], fb[rd][j][3]);
            }
        }
    };

    stage(0, 0); stage(1, 1);
    CPA_WAIT1(); __syncthreads();
    ldfrag(sb, 0, 0);

    int b = 0;
    for (int c = 0; c < NCH2; c++) {
        const uint32_t bufb = sb + (uint32_t)b * 32768u;
        stepld(bufb, 1, 0);
        stepld(bufb, 2, 1);
        stepld(bufb, 3, 0);
        if (c + 1 < NCH2) {
            CPA_WAIT0(); __syncthreads();
            int b2 = b + 2; if (b2 >= 3) b2 -= 3;
            if (c + 2 < NCH2) stage(c + 2, b2);
            int nb = b + 1; if (nb >= 3) nb -= 3;
            stepld(sb + (uint32_t)nb * 32768u, 0, 1);
        } else {
            do_mmas(acc, fa[1], fb[1]);
        }
        if (++b == 3) b = 0;
    }

    // Direct epilogue: m IS the pooled output row.
    #pragma unroll
    for (int mi = 0; mi < 4; mi++) {
        const int r0 = wm * 64 + mi * 16 + (lane >> 2);
        const int m0 = m_base + r0, m1 = m0 + 8;
        #pragma unroll
        for (int ni = 0; ni < 8; ni++) {
            const int cl = c_base + wn * 64 + ni * 8 + (lane & 3) * 2;
            const float* d = acc[mi][ni];
            *(float2*)(out + (size_t)m0 * 256 + cl) = make_float2(d[0], d[1]);
            *(float2*)(out + (size_t)m1 * 256 + cl) = make_float2(d[2], d[3]);
        }
    }
}

extern "C" void kernel_launch(void* const* d_in, const int* in_sizes, int n_in,
                              void* d_out, int out_size)
{
    const float* x  = (const float*)d_in[0];
    const float* wy = (const float*)d_in[1];
    const float* al = (const float*)d_in[2];
    const float* wl = (const float*)d_in[3];
    const float* wp = (const float*)d_in[4];
    float* out = (float*)d_out;

    cudaFuncSetAttribute(k1_yat, cudaFuncAttributeMaxDynamicSharedMemorySize, 98816);
    cudaFuncSetAttribute(k2_lin, cudaFuncAttributeMaxDynamicSharedMemorySize, 98304);

    k0a_t<<<dim3(8, 90), 256>>>(wy, wl, wp);
    k0s_bsum<<<256, 128>>>(wy);
    k0b_x<<<16384, 256>>>(x);
    k0c_asum<<<512, 256>>>();
    k1_yat<<<dim3(2, 1024), 128, 98816>>>(al);
    k2_lin<<<dim3(2, 256), 128, 98304>>>(out);
}